// round 15
// baseline (speedup 1.0000x reference)
#include <cuda_runtime.h>
#include <cuda_fp16.h>

// Problem constants (fixed by reference_code)
#define NN    48000     // total nodes
#define BB    16        // graphs
#define NPG   3000      // nodes per graph
#define EE    800000    // edges
#define DD    128       // feature dim (all layers)
#define KK    16        // base nodes per graph
#define DCOND 32
#define NC    2

#define NBLK  188       // ceil(NN/256)
#define SPAD  17        // uint32 stride per staged row (17*4=68 B; odd -> no bank conflicts)

// ---------------- device scratch (static, no runtime allocation) ----------------
// g_cnt is zero at module load and re-zeroed by k_scan3 every run (replay-safe).
__device__ float g_bufA[NN * DD];     // fp32 activations (layer input / agg output)
__device__ __half g_bufH[NN * DD];    // fp16 GEMM output (agg gather source), 12.3 MB
__device__ int   g_cnt[NN];           // in-degree histogram (self-restoring)
__device__ int   g_off[NN + 1];       // CSR row offsets (by dst)
__device__ int   g_cur[NN];           // scatter cursors
__device__ int   g_csrc[EE];          // CSR src indices
__device__ float g_isq[NN];           // deg^{-1/2} (deg includes self loop)
__device__ int   g_part[NBLK];        // scan partials
__device__ float g_xg[BB * DD];       // global mean pool
__device__ float g_z1[BB * DD];       // lin1 accumulator

// ---------------- f32x2 / f16x2 helpers ----------------
typedef unsigned long long u64t;

__device__ __forceinline__ u64t pk2(float lo, float hi) {
    u64t r; asm("mov.b64 %0, {%1, %2};" : "=l"(r) : "f"(lo), "f"(hi)); return r;
}
__device__ __forceinline__ u64t pkb(float x) {   // broadcast pack
    u64t r; asm("mov.b64 %0, {%1, %1};" : "=l"(r) : "f"(x)); return r;
}
__device__ __forceinline__ void unpk2(u64t v, float& lo, float& hi) {
    asm("mov.b64 {%0, %1}, %2;" : "=f"(lo), "=f"(hi) : "l"(v));
}
__device__ __forceinline__ void ffma2(u64t& d, u64t a, u64t b) {
    asm("fma.rn.f32x2 %0, %1, %2, %0;" : "+l"(d) : "l"(a), "l"(b));
}
__device__ __forceinline__ u64t fadd2(u64t a, u64t b) {
    u64t r; asm("add.rn.f32x2 %0, %1, %2;" : "=l"(r) : "l"(a), "l"(b)); return r;
}
// pack two fp32 -> fp16x2 (lo = first arg)
__device__ __forceinline__ unsigned int pkh2(float lo, float hi) {
    unsigned int r;
    asm("cvt.rn.f16x2.f32 %0, %1, %2;" : "=r"(r) : "f"(hi), "f"(lo));
    return r;
}

// ---------------- CSR build ----------------
__global__ void k_hist(const int* __restrict__ dst) {
    int e = blockIdx.x * 256 + threadIdx.x;
    if (e < EE) atomicAdd(&g_cnt[dst[e]], 1);
}

__global__ void k_scan1() {   // per-block sums + isq + zero readout accumulators
    __shared__ int sh[256];
    int t = threadIdx.x;
    int i = blockIdx.x * 256 + t;
    int c = (i < NN) ? g_cnt[i] : 0;
    if (i < NN) g_isq[i] = rsqrtf((float)c + 1.0f);
    if (i < BB * DD) { g_z1[i] = 0.f; g_xg[i] = 0.f; }
    sh[t] = c;
    __syncthreads();
    for (int d = 128; d > 0; d >>= 1) {
        if (t < d) sh[t] += sh[t + d];
        __syncthreads();
    }
    if (t == 0) g_part[blockIdx.x] = sh[0];
}

// Fused: block reduces partials[0..bid) for base offset, then local scan.
// Restores g_cnt to zero for the next replay.
__global__ void k_scan3() {
    __shared__ int sh[256];
    __shared__ int base_off;
    int t = threadIdx.x;

    int s = 0;
    for (int p = t; p < blockIdx.x; p += 256) s += g_part[p];
    sh[t] = s;
    __syncthreads();
    for (int d = 128; d > 0; d >>= 1) {
        if (t < d) sh[t] += sh[t + d];
        __syncthreads();
    }
    if (t == 0) base_off = sh[0];
    __syncthreads();

    int i = blockIdx.x * 256 + t;
    int c = (i < NN) ? g_cnt[i] : 0;
    sh[t] = c;
    __syncthreads();
    for (int d = 1; d < 256; d <<= 1) {
        int x = (t >= d) ? sh[t - d] : 0;
        __syncthreads();
        sh[t] += x;
        __syncthreads();
    }
    if (i < NN) {
        int off = base_off + sh[t] - c;
        g_off[i] = off;
        g_cur[i] = off;
        g_cnt[i] = 0;                 // self-restore for next replay
    }
    if (blockIdx.x == 0 && t == 0) g_off[NN] = EE;
}

__global__ void k_scatter(const int* __restrict__ src, const int* __restrict__ dst) {
    int e = blockIdx.x * 256 + threadIdx.x;
    if (e < EE) {
        int d = dst[e];
        int p = atomicAdd(&g_cur[d], 1);
        g_csrc[p] = src[e];
    }
}

// ---------------- GEMM: H[48000,128] fp16 = A[48000,128] fp32 @ W[128,128] ----------------
// 64-row x 128-col tile, 256 threads, 4x8 register micro-tile via packed f32x2.
// 96 KB smem -> 2 blocks/SM. FFMA2-pipe bound. Output packed fp16.
__global__ void __launch_bounds__(256, 2) k_gemm(const float* __restrict__ A,
                                                 const float* __restrict__ W,
                                                 __half* __restrict__ C) {
    extern __shared__ float sh[];
    float* Ws = sh;               // 128*128 = 64 KB
    float* As = sh + DD * DD;     // 64*128  = 32 KB
    int tid = threadIdx.x;
    int row0 = blockIdx.x * 64;

    {   // stage W (4096 float4) and A tile (2048 float4)
        const float4* W4 = (const float4*)W;
        const float4* A4 = (const float4*)(A + (size_t)row0 * DD);
        float4* Ws4 = (float4*)Ws;
        float4* As4 = (float4*)As;
#pragma unroll
        for (int i = 0; i < 16; i++) Ws4[tid + 256 * i] = W4[tid + 256 * i];
#pragma unroll
        for (int i = 0; i < 8; i++)  As4[tid + 256 * i] = A4[tid + 256 * i];
    }
    __syncthreads();

    int tcol = tid & 15;          // 16 col-groups of 8
    int trow = tid >> 4;          // 16 row-groups of 4
    u64t acc[4][4];               // 4 rows x 4 col-pairs (8 cols)
#pragma unroll
    for (int r = 0; r < 4; r++)
#pragma unroll
        for (int c = 0; c < 4; c++) acc[r][c] = 0ull;

    const float* a_base = &As[(trow * 4) * DD];
    const float* w_base = &Ws[tcol * 8];

#pragma unroll 4
    for (int k4 = 0; k4 < DD; k4 += 4) {
        float4 a4[4];
#pragma unroll
        for (int r = 0; r < 4; r++)
            a4[r] = *(const float4*)(a_base + r * DD + k4);
#pragma unroll
        for (int kk = 0; kk < 4; kk++) {
            const float4* wp = (const float4*)(w_base + (k4 + kk) * DD);
            float4 w0 = wp[0];
            float4 w1 = wp[1];
            u64t wv[4];
            wv[0] = pk2(w0.x, w0.y); wv[1] = pk2(w0.z, w0.w);
            wv[2] = pk2(w1.x, w1.y); wv[3] = pk2(w1.z, w1.w);
#pragma unroll
            for (int r = 0; r < 4; r++) {
                float av = (kk == 0) ? a4[r].x : (kk == 1) ? a4[r].y
                         : (kk == 2) ? a4[r].z : a4[r].w;
                u64t ab = pkb(av);
#pragma unroll
                for (int c = 0; c < 4; c++) ffma2(acc[r][c], ab, wv[c]);
            }
        }
    }

#pragma unroll
    for (int r = 0; r < 4; r++) {
        float o[8];
#pragma unroll
        for (int c = 0; c < 4; c++) unpk2(acc[r][c], o[2 * c], o[2 * c + 1]);
        uint4 st;
        st.x = pkh2(o[0], o[1]);
        st.y = pkh2(o[2], o[3]);
        st.z = pkh2(o[4], o[5]);
        st.w = pkh2(o[6], o[7]);
        *(uint4*)&C[(size_t)(row0 + trow * 4 + r) * DD + tcol * 8] = st;
    }
}

// ---------------- Aggregation: smem-staged per (graph, col-quarter, node-chunk) ----------------
// Block stages its graph's 32-column fp16 slice (3000 x 17 u32, stride-padded) in
// ~200 KB smem, then gathers from LDS (29 cyc) instead of L2 (~250-600 cyc).
// Half-warp per edge: 16 lanes x u32 (2 cols). 2 edges per warp step.
// out[d] = sum_e hw[src_e]*isq[s]*isq[d] + hw[d]*isq[d]^2 + bias ; optional ReLU
__global__ void __launch_bounds__(1024, 1) k_agg_sm(const __half* __restrict__ HW,
                                                    float* __restrict__ OUT,
                                                    const float* __restrict__ bias,
                                                    int do_relu) {
    extern __shared__ unsigned int sm[];
    int b = blockIdx.x;
    int g  = b >> 3;          // 16 graphs
    int q  = (b >> 1) & 3;    // 4 column quarters
    int ch = b & 1;           // 2 node chunks
    int gbase = g * NPG;
    int tid = threadIdx.x;

    // Fill: quarter q of graph g -> smem (coalesced 64-B row reads)
    const unsigned int* H32 = (const unsigned int*)HW;   // 64 u32 per node row
    for (int i = tid; i < NPG * 16; i += 1024) {
        int n = i >> 4, c = i & 15;
        sm[n * SPAD + c] = H32[(size_t)(gbase + n) * 64 + q * 16 + c];
    }
    __syncthreads();

    int warp = tid >> 5, lane = tid & 31;
    int hsel = lane >> 4;     // half-warp: 0 -> even-step edges, 1 -> odd
    int cl = lane & 15;       // column pair within quarter

    int nstart = gbase + ch * (NPG / 2);
    int nend = nstart + NPG / 2;

    for (int node = nstart + warp; node < nend; node += 32) {
        float isqd = g_isq[node];
        float sc = isqd * isqd;
        u64t acc = 0ull;

        int e0 = g_off[node], e1 = g_off[node + 1];
        for (int e = e0; e < e1; e += 32) {
            int m = min(32, e1 - e);
            int s = 0; float nn = 0.f;
            if (lane < m) {
                s = g_csrc[e + lane];
                nn = g_isq[s] * isqd;
            }
            for (int j = 0; j < m; j += 2) {
                int idx = j + hsel;                    // <= 31 always
                int   ssel = __shfl_sync(0xffffffffu, s, idx);
                float w    = __shfl_sync(0xffffffffu, nn, idx);
                // Tail guard: clamp BOTH value and address. Lanes where idx >= m
                // would otherwise compute row = 0 - gbase (negative -> OOB smem).
                int row = (idx < m) ? (ssel - gbase) : 0;
                if (idx >= m) w = 0.f;
                unsigned int v = sm[row * SPAD + cl];
                float2 f = __half22float2(*(const __half2*)&v);
                ffma2(acc, pk2(f.x, f.y), pkb(w));
            }
        }
        // combine even/odd halves (lane l += lane l^16)
        {
            unsigned int alo = (unsigned int)acc, ahi = (unsigned int)(acc >> 32);
            unsigned int blo = __shfl_xor_sync(0xffffffffu, alo, 16);
            unsigned int bhi = __shfl_xor_sync(0xffffffffu, ahi, 16);
            acc = fadd2(acc, ((u64t)bhi << 32) | (u64t)blo);
        }
        // self-loop + bias + store (low half only; 16 lanes x 8 B = 128-B row quarter)
        if (hsel == 0) {
            unsigned int v = sm[(node - gbase) * SPAD + cl];
            float2 f = __half22float2(*(const __half2*)&v);
            ffma2(acc, pk2(f.x, f.y), pkb(sc));
            float lo, hi;
            unpk2(acc, lo, hi);
            float2 bv = ((const float2*)bias)[q * 16 + cl];
            lo += bv.x; hi += bv.y;
            if (do_relu) { lo = fmaxf(lo, 0.f); hi = fmaxf(hi, 0.f); }
            ((u64t*)OUT)[(size_t)node * 64 + q * 16 + cl] = pk2(lo, hi);
        }
    }
}

// ---------------- Global mean pool: 16 graphs x 8 chunks ----------------
__global__ void k_pool(const float* __restrict__ H) {
    int g = blockIdx.x, ch = blockIdx.y, t = threadIdx.x;
    const float* p = H + ((size_t)g * NPG + ch * (NPG / 8)) * DD + t;
    float s = 0.f;
#pragma unroll 5
    for (int i = 0; i < NPG / 8; i++) s += p[(size_t)i * DD];
    atomicAdd(&g_xg[g * DD + t], s * (1.0f / NPG));
}

// ---------------- lin1: z[16,2176] @ W[2176,128], split over i-dimension ----------------
__global__ void k_lin1(const float* __restrict__ H, const int* __restrict__ base,
                       const float* __restrict__ W1) {
    __shared__ float zsh[BB * 128];   // this block's z slice
    int t = threadIdx.x;
    int i0 = blockIdx.x * 128;        // 17 blocks cover i in [0,2176)

    for (int idx = t; idx < BB * 128; idx += 128) {
        int g = idx >> 7, ii = idx & 127;
        int i = i0 + ii;
        float v;
        if (i < KK * DD) {            // selective gather part x_s
            int k = i >> 7, d = i & 127;
            int bn = base[g * KK + k];
            v = (bn > 0) ? H[((size_t)g * NPG + bn) * DD + d] : 0.f;
        } else {                      // global pool part x_g
            v = g_xg[g * DD + (i - KK * DD)];
        }
        zsh[idx] = v;
    }
    __syncthreads();

    float acc[BB];
#pragma unroll
    for (int g = 0; g < BB; g++) acc[g] = 0.f;
    for (int ii = 0; ii < 128; ii++) {
        float w = W1[(size_t)(i0 + ii) * DD + t];
#pragma unroll
        for (int g = 0; g < BB; g++) acc[g] = fmaf(zsh[g * 128 + ii], w, acc[g]);
    }
#pragma unroll
    for (int g = 0; g < BB; g++) atomicAdd(&g_z1[g * DD + t], acc[g]);
}

// ---------------- final: relu(z1 + b) concat cond -> lin2 -> out[16,2] ----------------
__global__ void k_final(const float* __restrict__ lin1_b, const float* __restrict__ cond,
                        const float* __restrict__ W2, const float* __restrict__ b2,
                        float* __restrict__ out) {
    int t = threadIdx.x;
    if (t >= BB * NC) return;
    int g = t >> 1, c = t & 1;
    float acc = b2[c];
    for (int j = 0; j < DD; j++) {
        float z = fmaxf(g_z1[g * DD + j] + lin1_b[j], 0.f);
        acc = fmaf(z, W2[j * NC + c], acc);
    }
    for (int j = 0; j < DCOND; j++)
        acc = fmaf(cond[g * DCOND + j], W2[(DD + j) * NC + c], acc);
    out[g * NC + c] = acc;
}

// ---------------- launch ----------------
extern "C" void kernel_launch(void* const* d_in, const int* in_sizes, int n_in,
                              void* d_out, int out_size) {
    const float* x      = (const float*)d_in[0];
    const int*   ei     = (const int*)d_in[1];
    const int*   src    = ei;
    const int*   dst    = ei + EE;
    const int*   base   = (const int*)d_in[3];
    const float* cond   = (const float*)d_in[4];
    const float* W[5]   = {(const float*)d_in[5], (const float*)d_in[7],
                           (const float*)d_in[9], (const float*)d_in[11],
                           (const float*)d_in[13]};
    const float* bias[5] = {(const float*)d_in[6], (const float*)d_in[8],
                            (const float*)d_in[10], (const float*)d_in[12],
                            (const float*)d_in[14]};
    const float* lin1_W = (const float*)d_in[15];
    const float* lin1_b = (const float*)d_in[16];
    const float* lin2_W = (const float*)d_in[17];
    const float* lin2_b = (const float*)d_in[18];
    float* out = (float*)d_out;

    // dynamic SMEM opt-ins (idempotent; capture-safe)
    cudaFuncSetAttribute(k_gemm, cudaFuncAttributeMaxDynamicSharedMemorySize, 98304);
    cudaFuncSetAttribute(k_agg_sm, cudaFuncAttributeMaxDynamicSharedMemorySize, NPG * SPAD * 4);

    void *pa, *ph;
    cudaGetSymbolAddress(&pa, g_bufA);
    cudaGetSymbolAddress(&ph, g_bufH);
    float*  A = (float*)pa;
    __half* H = (__half*)ph;

    // CSR build; layer-0 GEMM hoisted before scatter (depends only on x) so the
    // ncu capture window lands on k_gemm.
    k_hist<<<EE / 256, 256>>>(dst);
    k_scan1<<<NBLK, 256>>>();
    k_scan3<<<NBLK, 256>>>();
    k_gemm<<<NN / 64, 256, 98304>>>(x, W[0], H);
    k_scatter<<<EE / 256, 256>>>(src, dst);

    // 5 GCN layers: gemm (fp32 in -> fp16 out), smem-staged agg (fp16 -> fp32)
    k_agg_sm<<<BB * 4 * 2, 1024, NPG * SPAD * 4>>>(H, A, bias[0], 1);
    for (int l = 1; l < 5; l++) {
        k_gemm<<<NN / 64, 256, 98304>>>(A, W[l], H);
        k_agg_sm<<<BB * 4 * 2, 1024, NPG * SPAD * 4>>>(H, A, bias[l], (l < 4) ? 1 : 0);
    }

    // readout
    k_pool<<<dim3(BB, 8), 128>>>(A);
    k_lin1<<<17, 128>>>(A, base, lin1_W);
    k_final<<<1, 32>>>(lin1_b, cond, lin2_W, lin2_b, out);
}

// round 16
// speedup vs baseline: 1.5535x; 1.5535x over previous
#include <cuda_runtime.h>
#include <cuda_fp16.h>

// Problem constants (fixed by reference_code)
#define NN    48000     // total nodes
#define BB    16        // graphs
#define NPG   3000      // nodes per graph
#define EE    800000    // edges
#define DD    128       // feature dim (all layers)
#define KK    16        // base nodes per graph
#define DCOND 32
#define NC    2

#define NBLK  188       // ceil(NN/256)

// ---------------- device scratch (static, no runtime allocation) ----------------
// g_cnt is zero at module load and re-zeroed by k_scan3 every run (replay-safe).
__device__ float g_bufA[NN * DD];     // fp32 activations (layer input / agg output)
__device__ __half g_bufH[NN * DD];    // fp16 GEMM output (agg gather source), 12.3 MB
__device__ int   g_cnt[NN];           // in-degree histogram (self-restoring)
__device__ int   g_off[NN + 1];       // CSR row offsets (by dst)
__device__ int   g_cur[NN];           // scatter cursors
__device__ int   g_csrc[EE];          // CSR src indices
__device__ float g_isq[NN];           // deg^{-1/2} (deg includes self loop)
__device__ int   g_part[NBLK];        // scan partials
__device__ float g_xg[BB * DD];       // global mean pool
__device__ float g_z1[BB * DD];       // lin1 accumulator

// ---------------- f32x2 / f16x2 helpers ----------------
typedef unsigned long long u64t;

__device__ __forceinline__ u64t pk2(float lo, float hi) {
    u64t r; asm("mov.b64 %0, {%1, %2};" : "=l"(r) : "f"(lo), "f"(hi)); return r;
}
__device__ __forceinline__ u64t pkb(float x) {   // broadcast pack
    u64t r; asm("mov.b64 %0, {%1, %1};" : "=l"(r) : "f"(x)); return r;
}
__device__ __forceinline__ void unpk2(u64t v, float& lo, float& hi) {
    asm("mov.b64 {%0, %1}, %2;" : "=f"(lo), "=f"(hi) : "l"(v));
}
__device__ __forceinline__ void ffma2(u64t& d, u64t a, u64t b) {
    asm("fma.rn.f32x2 %0, %1, %2, %0;" : "+l"(d) : "l"(a), "l"(b));
}
__device__ __forceinline__ u64t fadd2(u64t a, u64t b) {
    u64t r; asm("add.rn.f32x2 %0, %1, %2;" : "=l"(r) : "l"(a), "l"(b)); return r;
}
// pack two fp32 -> fp16x2 (lo = first arg)
__device__ __forceinline__ unsigned int pkh2(float lo, float hi) {
    unsigned int r;
    asm("cvt.rn.f16x2.f32 %0, %1, %2;" : "=r"(r) : "f"(hi), "f"(lo));
    return r;
}

// ---------------- CSR build ----------------
__global__ void k_hist(const int* __restrict__ dst) {
    int e = blockIdx.x * 256 + threadIdx.x;
    if (e < EE) atomicAdd(&g_cnt[dst[e]], 1);
}

__global__ void k_scan1() {   // per-block sums + isq + zero readout accumulators
    __shared__ int sh[256];
    int t = threadIdx.x;
    int i = blockIdx.x * 256 + t;
    int c = (i < NN) ? g_cnt[i] : 0;
    if (i < NN) g_isq[i] = rsqrtf((float)c + 1.0f);
    if (i < BB * DD) { g_z1[i] = 0.f; g_xg[i] = 0.f; }
    sh[t] = c;
    __syncthreads();
    for (int d = 128; d > 0; d >>= 1) {
        if (t < d) sh[t] += sh[t + d];
        __syncthreads();
    }
    if (t == 0) g_part[blockIdx.x] = sh[0];
}

// Fused: block reduces partials[0..bid) for base offset, then local scan.
// Restores g_cnt to zero for the next replay.
__global__ void k_scan3() {
    __shared__ int sh[256];
    __shared__ int base_off;
    int t = threadIdx.x;

    int s = 0;
    for (int p = t; p < blockIdx.x; p += 256) s += g_part[p];
    sh[t] = s;
    __syncthreads();
    for (int d = 128; d > 0; d >>= 1) {
        if (t < d) sh[t] += sh[t + d];
        __syncthreads();
    }
    if (t == 0) base_off = sh[0];
    __syncthreads();

    int i = blockIdx.x * 256 + t;
    int c = (i < NN) ? g_cnt[i] : 0;
    sh[t] = c;
    __syncthreads();
    for (int d = 1; d < 256; d <<= 1) {
        int x = (t >= d) ? sh[t - d] : 0;
        __syncthreads();
        sh[t] += x;
        __syncthreads();
    }
    if (i < NN) {
        int off = base_off + sh[t] - c;
        g_off[i] = off;
        g_cur[i] = off;
        g_cnt[i] = 0;                 // self-restore for next replay
    }
    if (blockIdx.x == 0 && t == 0) g_off[NN] = EE;
}

__global__ void k_scatter(const int* __restrict__ src, const int* __restrict__ dst) {
    int e = blockIdx.x * 256 + threadIdx.x;
    if (e < EE) {
        int d = dst[e];
        int p = atomicAdd(&g_cur[d], 1);
        g_csrc[p] = src[e];
    }
}

// ---------------- GEMM: H[48000,128] fp16 = A[48000,128] fp32 @ W[128,128] ----------------
// 128-row x 128-col tile, 256 threads, 8x8 micro-tile. A and W staged as fp16
// half2 in smem (64 KB total) -> ~1 B of LDS per FFMA2 (was 3) -> fma-pipe bound.
// Compute in fp32 via f32x2 after inline half2->float2 conversion.
__global__ void __launch_bounds__(256, 2) k_gemm(const float* __restrict__ A,
                                                 const float* __restrict__ W,
                                                 __half* __restrict__ C) {
    extern __shared__ unsigned int s32[];
    unsigned int* As32 = s32;              // [128][64] half2 words, 32 KB
    unsigned int* Ws32 = s32 + 128 * 64;   // [128][64] half2 words, 32 KB
    int tid = threadIdx.x;
    int row0 = blockIdx.x * 128;

    // Stage both tiles as fp16 (coalesced float2 reads -> half2 writes)
#pragma unroll
    for (int i = 0; i < 32; i++) {
        int idx = i * 256 + tid;           // 8192 half2 words each
        int row = idx >> 6, cp = idx & 63;
        float2 av = *(const float2*)(A + (size_t)(row0 + row) * DD + cp * 2);
        As32[idx] = pkh2(av.x, av.y);
        float2 wv = *(const float2*)(W + row * DD + cp * 2);   // row = k index
        Ws32[idx] = pkh2(wv.x, wv.y);
    }
    __syncthreads();

    int tcol = tid & 15;          // 16 col-groups of 8
    int trow = tid >> 4;          // 16 row-groups of 8
    u64t acc[8][4];               // 8 rows x 4 col-pairs
#pragma unroll
    for (int r = 0; r < 8; r++)
#pragma unroll
        for (int c = 0; c < 4; c++) acc[r][c] = 0ull;

    const unsigned int* a_base = &As32[(trow * 8) * 64];
    const unsigned int* w_base = &Ws32[tcol * 4];

#pragma unroll 4
    for (int kc = 0; kc < 32; kc++) {      // 4 k per chunk
        uint2 ar[8];                        // 8 rows x 4 k-halves
#pragma unroll
        for (int r = 0; r < 8; r++)
            ar[r] = *(const uint2*)(a_base + r * 64 + kc * 2);
#pragma unroll
        for (int kk = 0; kk < 4; kk++) {
            uint4 wq = *(const uint4*)(w_base + (kc * 4 + kk) * 64);
            u64t wv[4];
            {
                float2 f;
                f = __half22float2(*(const __half2*)&wq.x); wv[0] = pk2(f.x, f.y);
                f = __half22float2(*(const __half2*)&wq.y); wv[1] = pk2(f.x, f.y);
                f = __half22float2(*(const __half2*)&wq.z); wv[2] = pk2(f.x, f.y);
                f = __half22float2(*(const __half2*)&wq.w); wv[3] = pk2(f.x, f.y);
            }
#pragma unroll
            for (int r = 0; r < 8; r++) {
                unsigned int au = (kk < 2) ? ar[r].x : ar[r].y;
                float2 af = __half22float2(*(const __half2*)&au);  // CSE'd across kk pair
                float aval = (kk & 1) ? af.y : af.x;
                u64t ab = pkb(aval);
#pragma unroll
                for (int c = 0; c < 4; c++) ffma2(acc[r][c], ab, wv[c]);
            }
        }
    }

#pragma unroll
    for (int r = 0; r < 8; r++) {
        float o[8];
#pragma unroll
        for (int c = 0; c < 4; c++) unpk2(acc[r][c], o[2 * c], o[2 * c + 1]);
        uint4 st;
        st.x = pkh2(o[0], o[1]);
        st.y = pkh2(o[2], o[3]);
        st.z = pkh2(o[4], o[5]);
        st.w = pkh2(o[6], o[7]);
        *(uint4*)&C[(size_t)(row0 + trow * 8 + r) * DD + tcol * 8] = st;
    }
}

// ---------------- Aggregation: warp per dst node, fp16 L2 gather (proven R12 shape) ----------------
// out[d] = sum_e hw[src_e]*isq[s]*isq[d] + hw[d]*isq[d]^2 + bias ; optional ReLU
__global__ void __launch_bounds__(128) k_agg(const __half* __restrict__ HW,
                                             float* __restrict__ OUT,
                                             const float* __restrict__ bias, int do_relu) {
    int warp = threadIdx.x >> 5;
    int lane = threadIdx.x & 31;
    int node = blockIdx.x * 4 + warp;

    const uint2* hw = (const uint2*)HW;   // 4 halves per lane, 32 lanes = 256 B/row
    float isqd = g_isq[node];
    float sc = isqd * isqd;

    // self-loop term
    uint2 sv = hw[(size_t)node * 32 + lane];
    float2 s01 = __half22float2(*(const __half2*)&sv.x);
    float2 s23 = __half22float2(*(const __half2*)&sv.y);
    u64t acc0a = pk2(s01.x * sc, s01.y * sc);
    u64t acc0b = pk2(s23.x * sc, s23.y * sc);
    u64t acc1a = 0ull, acc1b = 0ull;

    int e0 = g_off[node], e1 = g_off[node + 1];
    for (int e = e0; e < e1; e += 32) {
        int m = min(32, e1 - e);
        int s = 0; float nn = 0.f;
        if (lane < m) {
            s = g_csrc[e + lane];
            nn = g_isq[s] * isqd;       // g_isq slice is L1-resident (12 KB/graph)
        }
        int j = 0;
        for (; j + 1 < m; j += 2) {
            int   s0 = __shfl_sync(0xffffffffu, s, j);
            int   s1 = __shfl_sync(0xffffffffu, s, j + 1);
            float w0 = __shfl_sync(0xffffffffu, nn, j);
            float w1 = __shfl_sync(0xffffffffu, nn, j + 1);
            uint2 v0 = hw[(size_t)s0 * 32 + lane];
            uint2 v1 = hw[(size_t)s1 * 32 + lane];
            float2 a01 = __half22float2(*(const __half2*)&v0.x);
            float2 a23 = __half22float2(*(const __half2*)&v0.y);
            float2 b01 = __half22float2(*(const __half2*)&v1.x);
            float2 b23 = __half22float2(*(const __half2*)&v1.y);
            u64t wb0 = pkb(w0), wb1 = pkb(w1);
            ffma2(acc0a, pk2(a01.x, a01.y), wb0);
            ffma2(acc0b, pk2(a23.x, a23.y), wb0);
            ffma2(acc1a, pk2(b01.x, b01.y), wb1);
            ffma2(acc1b, pk2(b23.x, b23.y), wb1);
        }
        if (j < m) {
            int   s0 = __shfl_sync(0xffffffffu, s, j);
            float w0 = __shfl_sync(0xffffffffu, nn, j);
            uint2 v0 = hw[(size_t)s0 * 32 + lane];
            float2 a01 = __half22float2(*(const __half2*)&v0.x);
            float2 a23 = __half22float2(*(const __half2*)&v0.y);
            u64t wb0 = pkb(w0);
            ffma2(acc0a, pk2(a01.x, a01.y), wb0);
            ffma2(acc0b, pk2(a23.x, a23.y), wb0);
        }
    }
    u64t ra = fadd2(acc0a, acc1a);
    u64t rb = fadd2(acc0b, acc1b);
    float4 r;
    unpk2(ra, r.x, r.y);
    unpk2(rb, r.z, r.w);
    float4 bv = ((const float4*)bias)[lane];
    r.x += bv.x; r.y += bv.y; r.z += bv.z; r.w += bv.w;
    if (do_relu) {
        r.x = fmaxf(r.x, 0.f); r.y = fmaxf(r.y, 0.f);
        r.z = fmaxf(r.z, 0.f); r.w = fmaxf(r.w, 0.f);
    }
    ((float4*)OUT)[(size_t)node * 32 + lane] = r;
}

// ---------------- Global mean pool: 16 graphs x 8 chunks ----------------
__global__ void k_pool(const float* __restrict__ H) {
    int g = blockIdx.x, ch = blockIdx.y, t = threadIdx.x;
    const float* p = H + ((size_t)g * NPG + ch * (NPG / 8)) * DD + t;
    float s = 0.f;
#pragma unroll 5
    for (int i = 0; i < NPG / 8; i++) s += p[(size_t)i * DD];
    atomicAdd(&g_xg[g * DD + t], s * (1.0f / NPG));
}

// ---------------- lin1: z[16,2176] @ W[2176,128], split over i-dimension ----------------
__global__ void k_lin1(const float* __restrict__ H, const int* __restrict__ base,
                       const float* __restrict__ W1) {
    __shared__ float zsh[BB * 128];   // this block's z slice
    int t = threadIdx.x;
    int i0 = blockIdx.x * 128;        // 17 blocks cover i in [0,2176)

    for (int idx = t; idx < BB * 128; idx += 128) {
        int g = idx >> 7, ii = idx & 127;
        int i = i0 + ii;
        float v;
        if (i < KK * DD) {            // selective gather part x_s
            int k = i >> 7, d = i & 127;
            int bn = base[g * KK + k];
            v = (bn > 0) ? H[((size_t)g * NPG + bn) * DD + d] : 0.f;
        } else {                      // global pool part x_g
            v = g_xg[g * DD + (i - KK * DD)];
        }
        zsh[idx] = v;
    }
    __syncthreads();

    float acc[BB];
#pragma unroll
    for (int g = 0; g < BB; g++) acc[g] = 0.f;
    for (int ii = 0; ii < 128; ii++) {
        float w = W1[(size_t)(i0 + ii) * DD + t];
#pragma unroll
        for (int g = 0; g < BB; g++) acc[g] = fmaf(zsh[g * 128 + ii], w, acc[g]);
    }
#pragma unroll
    for (int g = 0; g < BB; g++) atomicAdd(&g_z1[g * DD + t], acc[g]);
}

// ---------------- final: relu(z1 + b) concat cond -> lin2 -> out[16,2] ----------------
__global__ void k_final(const float* __restrict__ lin1_b, const float* __restrict__ cond,
                        const float* __restrict__ W2, const float* __restrict__ b2,
                        float* __restrict__ out) {
    int t = threadIdx.x;
    if (t >= BB * NC) return;
    int g = t >> 1, c = t & 1;
    float acc = b2[c];
    for (int j = 0; j < DD; j++) {
        float z = fmaxf(g_z1[g * DD + j] + lin1_b[j], 0.f);
        acc = fmaf(z, W2[j * NC + c], acc);
    }
    for (int j = 0; j < DCOND; j++)
        acc = fmaf(cond[g * DCOND + j], W2[(DD + j) * NC + c], acc);
    out[g * NC + c] = acc;
}

// ---------------- launch ----------------
extern "C" void kernel_launch(void* const* d_in, const int* in_sizes, int n_in,
                              void* d_out, int out_size) {
    const float* x      = (const float*)d_in[0];
    const int*   ei     = (const int*)d_in[1];
    const int*   src    = ei;
    const int*   dst    = ei + EE;
    const int*   base   = (const int*)d_in[3];
    const float* cond   = (const float*)d_in[4];
    const float* W[5]   = {(const float*)d_in[5], (const float*)d_in[7],
                           (const float*)d_in[9], (const float*)d_in[11],
                           (const float*)d_in[13]};
    const float* bias[5] = {(const float*)d_in[6], (const float*)d_in[8],
                            (const float*)d_in[10], (const float*)d_in[12],
                            (const float*)d_in[14]};
    const float* lin1_W = (const float*)d_in[15];
    const float* lin1_b = (const float*)d_in[16];
    const float* lin2_W = (const float*)d_in[17];
    const float* lin2_b = (const float*)d_in[18];
    float* out = (float*)d_out;

    // 64 KB dynamic SMEM for the GEMM (idempotent; capture-safe)
    cudaFuncSetAttribute(k_gemm, cudaFuncAttributeMaxDynamicSharedMemorySize, 65536);

    void *pa, *ph;
    cudaGetSymbolAddress(&pa, g_bufA);
    cudaGetSymbolAddress(&ph, g_bufH);
    float*  A = (float*)pa;
    __half* H = (__half*)ph;

    // CSR build; layer-0 GEMM hoisted before scatter (depends only on x) so the
    // ncu capture window lands on k_gemm.
    k_hist<<<EE / 256, 256>>>(dst);
    k_scan1<<<NBLK, 256>>>();
    k_scan3<<<NBLK, 256>>>();
    k_gemm<<<NN / 128, 256, 65536>>>(x, W[0], H);
    k_scatter<<<EE / 256, 256>>>(src, dst);

    // 5 GCN layers: gemm (fp32 in -> fp16 out), agg (fp16 gather -> fp32 out)
    k_agg<<<NN / 4, 128>>>(H, A, bias[0], 1);
    for (int l = 1; l < 5; l++) {
        k_gemm<<<NN / 128, 256, 65536>>>(A, W[l], H);
        k_agg<<<NN / 4, 128>>>(H, A, bias[l], (l < 4) ? 1 : 0);
    }

    // readout
    k_pool<<<dim3(BB, 8), 128>>>(A);
    k_lin1<<<17, 128>>>(A, base, lin1_W);
    k_final<<<1, 32>>>(lin1_b, cond, lin2_W, lin2_b, out);
}